// round 5
// baseline (speedup 1.0000x reference)
#include <cuda_runtime.h>
#include <cuda_fp16.h>
#include <cstdint>
#include <cstddef>

// Problem shape (fixed by setup_inputs)
#define M_DIM 2048
#define K_DIM 4096
#define N_DIM 11008
#define GS    128
#define NPACK 1376            // N/8

// Converted x (fp16, [M, K]) — only remaining scratch
__device__ __align__(16) __half g_xh[(size_t)M_DIM * K_DIM];

__device__ __forceinline__ uint32_t pack_h2(float a, float b) {
    __half2 h = __floats2half2_rn(a, b);
    return *reinterpret_cast<uint32_t*>(&h);
}
__device__ __forceinline__ uint32_t smem_u32(const void* p) {
    return (uint32_t)__cvta_generic_to_shared(p);
}

// ---------------------------------------------------------------------------
// Kernel 1: x fp32 -> fp16
// ---------------------------------------------------------------------------
__global__ __launch_bounds__(256)
void xconv_kernel(const float* __restrict__ x) {
    int idx = blockIdx.x * blockDim.x + threadIdx.x;
    if (idx >= (M_DIM * K_DIM) / 8) return;
    const float4* xf = reinterpret_cast<const float4*>(x);
    float4 a = xf[2 * idx];
    float4 b = xf[2 * idx + 1];
    uint4 out;
    out.x = pack_h2(a.x, a.y);
    out.y = pack_h2(a.z, a.w);
    out.z = pack_h2(b.x, b.y);
    out.w = pack_h2(b.z, b.w);
    *reinterpret_cast<uint4*>(&g_xh[(size_t)idx * 8]) = out;
}

// ---------------------------------------------------------------------------
// Kernel 2: fused dequant + fp16 GEMM (fp32 accum).
// C[M,N] = Xh[M,K] * dequant(qweight)[K,N]
// BM=128, BN=128, BK=32; 8 warps (2 x 4), warp tile 64x32, double-buffered.
// A: cp.async from g_xh. B: LDG packed int4 -> dequant in regs -> STS fp16.
// ---------------------------------------------------------------------------
#define BM 128
#define BN 128
#define BK 32
#define LDA 40    // halfs; conflict-free ldmatrix phases (validated round 1)
#define LDB 136   // halfs; conflict-free ldmatrix.trans phases

__global__ __launch_bounds__(256, 2)
void gemm_fused_kernel(const int* __restrict__ qw,
                       const int* __restrict__ qz,
                       const float* __restrict__ sc,
                       float* __restrict__ C) {
    __shared__ __half As[2][BM * LDA];
    __shared__ __half Bs[2][BK * LDB];

    const int tid  = threadIdx.x;
    const int warp = tid >> 5;
    const int lane = tid & 31;
    const int wm   = warp >> 2;   // 0..1
    const int wn   = warp & 3;    // 0..3
    const int bm   = blockIdx.y * BM;
    const int bn   = blockIdx.x * BN;

    float acc[4][4][4];
#pragma unroll
    for (int i = 0; i < 4; i++)
#pragma unroll
        for (int j = 0; j < 4; j++)
#pragma unroll
            for (int r = 0; r < 4; r++) acc[i][j][r] = 0.f;

    // ---- A producer indices (cp.async, 16B chunks) ----
    const int arow = tid >> 2, acol = (tid & 3) * 8;   // 128 rows x 4 chunks
    const __half* gA = g_xh + (size_t)bm * K_DIM;

    auto loadA = [&](int st, int k0) {
#pragma unroll
        for (int i = 0; i < 2; i++) {
            int r = arow + i * 64;
            uint32_t d = smem_u32(&As[st][r * LDA + acol]);
            const __half* s = gA + (size_t)r * K_DIM + k0 + acol;
            asm volatile("cp.async.cg.shared.global [%0], [%1], 16;\n" ::"r"(d), "l"(s));
        }
        asm volatile("cp.async.commit_group;\n");
    };

    // ---- B producer indices (fused dequant) ----
    // thread: packed col pc (0..15), base row r (0..15); handles rows r, r+16
    const int pc = tid & 15;
    const int r  = tid >> 4;
    const int cg = bn / 8 + pc;                    // global packed col
    const int sh[8] = {0, 16, 4, 20, 8, 24, 12, 28};

    const int* qw_ptr0 = qw + (size_t)r * NPACK + cg;          // advances 32 rows/stage
    const int* qw_ptr1 = qw_ptr0 + (size_t)16 * NPACK;
    const int* qz_ptr  = qz + cg;                              // + g*NPACK
    const float* sc_ptr = sc + (size_t)cg * 8;                 // + g*N_DIM

    // per-stage register bundle
    uint32_t qw0, qw1;
    float sv[8], zs[8];

    auto loadB = [&](int kt) {
        const size_t koff = (size_t)kt * 32 * NPACK;
        qw0 = (uint32_t)qw_ptr0[koff];
        qw1 = (uint32_t)qw_ptr1[koff];
        const int g = kt >> 2;
        const uint32_t z = (uint32_t)qz_ptr[(size_t)g * NPACK];
        const float4* sp = reinterpret_cast<const float4*>(sc_ptr + (size_t)g * N_DIM);
        float4 s0 = sp[0], s1 = sp[1];
        sv[0] = s0.x; sv[1] = s0.y; sv[2] = s0.z; sv[3] = s0.w;
        sv[4] = s1.x; sv[5] = s1.y; sv[6] = s1.z; sv[7] = s1.w;
#pragma unroll
        for (int m = 0; m < 8; m++)
            zs[m] = (float)(int)((z >> sh[m]) & 15) * sv[m];
    };

    auto stsB = [&](int st) {
#pragma unroll
        for (int j = 0; j < 2; j++) {
            const uint32_t w = j ? qw1 : qw0;
            float f[8];
#pragma unroll
            for (int m = 0; m < 8; m++)
                f[m] = fmaf((float)(int)((w >> sh[m]) & 15), sv[m], -zs[m]);
            uint4 o;
            o.x = pack_h2(f[0], f[1]);
            o.y = pack_h2(f[2], f[3]);
            o.z = pack_h2(f[4], f[5]);
            o.w = pack_h2(f[6], f[7]);
            *reinterpret_cast<uint4*>(&Bs[st][(r + j * 16) * LDB + pc * 8]) = o;
        }
    };

    // ---- prologue: stage 0 ----
    loadA(0, 0);
    loadB(0);
    stsB(0);
    asm volatile("cp.async.wait_group 0;\n");
    __syncthreads();

    const int NK = K_DIM / BK;   // 128
    for (int kt = 0; kt < NK; kt++) {
        const int st = kt & 1;
        const bool more = (kt + 1 < NK);
        if (more) {
            loadA(st ^ 1, (kt + 1) * BK);
            loadB(kt + 1);          // LDGs in flight across the MMA block
        }

        // ---- compute stage st ----
#pragma unroll
        for (int kp = 0; kp < 2; kp++) {
            uint32_t a[4][4];
            uint32_t b[4][2];
#pragma unroll
            for (int mi = 0; mi < 4; mi++) {
                int row = wm * 64 + mi * 16 + (lane & 15);
                int col = kp * 16 + (lane >> 4) * 8;
                uint32_t addr = smem_u32(&As[st][row * LDA + col]);
                asm volatile(
                    "ldmatrix.sync.aligned.x4.m8n8.shared.b16 {%0,%1,%2,%3}, [%4];"
                    : "=r"(a[mi][0]), "=r"(a[mi][1]), "=r"(a[mi][2]), "=r"(a[mi][3])
                    : "r"(addr));
            }
#pragma unroll
            for (int ni = 0; ni < 4; ni++) {
                int row = kp * 16 + (lane & 15);
                int col = wn * 32 + ni * 8;
                uint32_t addr = smem_u32(&Bs[st][row * LDB + col]);
                asm volatile(
                    "ldmatrix.sync.aligned.x2.trans.m8n8.shared.b16 {%0,%1}, [%2];"
                    : "=r"(b[ni][0]), "=r"(b[ni][1])
                    : "r"(addr));
            }
#pragma unroll
            for (int mi = 0; mi < 4; mi++)
#pragma unroll
                for (int ni = 0; ni < 4; ni++) {
                    asm volatile(
                        "mma.sync.aligned.m16n8k16.row.col.f32.f16.f16.f32 "
                        "{%0,%1,%2,%3}, {%4,%5,%6,%7}, {%8,%9}, {%0,%1,%2,%3};"
                        : "+f"(acc[mi][ni][0]), "+f"(acc[mi][ni][1]),
                          "+f"(acc[mi][ni][2]), "+f"(acc[mi][ni][3])
                        : "r"(a[mi][0]), "r"(a[mi][1]), "r"(a[mi][2]), "r"(a[mi][3]),
                          "r"(b[ni][0]), "r"(b[ni][1]));
                }
        }

        if (more) {
            stsB(st ^ 1);
            asm volatile("cp.async.wait_group 0;\n");
        }
        __syncthreads();
    }

    // ---- epilogue: fp32 C ----
#pragma unroll
    for (int mi = 0; mi < 4; mi++) {
        int row = bm + wm * 64 + mi * 16 + (lane >> 2);
#pragma unroll
        for (int ni = 0; ni < 4; ni++) {
            int col = bn + wn * 32 + ni * 8 + (lane & 3) * 2;
            float2* p0 = reinterpret_cast<float2*>(&C[(size_t)row * N_DIM + col]);
            float2* p1 = reinterpret_cast<float2*>(&C[(size_t)(row + 8) * N_DIM + col]);
            *p0 = make_float2(acc[mi][ni][0], acc[mi][ni][1]);
            *p1 = make_float2(acc[mi][ni][2], acc[mi][ni][3]);
        }
    }
}

// ---------------------------------------------------------------------------
// Launch: inputs (metadata order): x, qweight, qzeros, scales, group_size
// ---------------------------------------------------------------------------
extern "C" void kernel_launch(void* const* d_in, const int* in_sizes, int n_in,
                              void* d_out, int out_size) {
    const float* x   = (const float*)d_in[0];
    const int*   qw  = (const int*)d_in[1];
    const int*   qz  = (const int*)d_in[2];
    const float* sc  = (const float*)d_in[3];
    float*       out = (float*)d_out;

    {
        int total = (M_DIM * K_DIM) / 8;
        xconv_kernel<<<(total + 255) / 256, 256>>>(x);
    }
    {
        dim3 grid(N_DIM / BN, M_DIM / BM);   // 86 x 16
        gemm_fused_kernel<<<grid, 256>>>(qw, qz, sc, out);
    }
}